// round 1
// baseline (speedup 1.0000x reference)
#include <cuda_runtime.h>

#define N_ROWS 16384
#define D      1024
#define TEMPC  0.05f
#define EPSC   1e-8f

// Per-row loss scratch (device global: no allocation allowed in kernel_launch)
__device__ float g_row_loss[N_ROWS];

// One CTA per row. 256 threads x float4 = 1024 floats = one full row of each input.
__global__ __launch_bounds__(256) void byol_row_kernel(
    const float4* __restrict__ a4, const float4* __restrict__ b4)
{
    const int row = blockIdx.x;
    const int t   = threadIdx.x;

    const float4 av = a4[row * (D / 4) + t];
    const float4 bv = b4[row * (D / 4) + t];

    float dot = av.x * bv.x + av.y * bv.y + av.z * bv.z + av.w * bv.w;
    float aa  = av.x * av.x + av.y * av.y + av.z * av.z + av.w * av.w;
    float bb  = bv.x * bv.x + bv.y * bv.y + bv.z * bv.z + bv.w * bv.w;

    // Warp tree reduce (3 values)
    #pragma unroll
    for (int off = 16; off > 0; off >>= 1) {
        dot += __shfl_xor_sync(0xffffffffu, dot, off);
        aa  += __shfl_xor_sync(0xffffffffu, aa,  off);
        bb  += __shfl_xor_sync(0xffffffffu, bb,  off);
    }

    __shared__ float s_dot[8], s_aa[8], s_bb[8];
    const int wid = t >> 5, lid = t & 31;
    if (lid == 0) { s_dot[wid] = dot; s_aa[wid] = aa; s_bb[wid] = bb; }
    __syncthreads();

    if (t == 0) {
        float d = 0.f, x = 0.f, y = 0.f;
        #pragma unroll
        for (int w = 0; w < 8; w++) { d += s_dot[w]; x += s_aa[w]; y += s_bb[w]; }
        const float n1 = fmaxf(sqrtf(x), EPSC);
        const float n2 = fmaxf(sqrtf(y), EPSC);
        const float cosv = d / (n1 * n2);
        g_row_loss[row] = 2.0f - 2.0f * cosv;
    }
}

// Single-CTA deterministic final reduction: out = sum(row_loss)/(N*TEMP)
__global__ __launch_bounds__(1024) void byol_reduce_kernel(float* __restrict__ out)
{
    __shared__ float s[1024];
    const int t = threadIdx.x;
    float sum = 0.f;
    #pragma unroll
    for (int i = t; i < N_ROWS; i += 1024) sum += g_row_loss[i];
    s[t] = sum;
    __syncthreads();
    #pragma unroll
    for (int off = 512; off > 0; off >>= 1) {
        if (t < off) s[t] += s[t + off];
        __syncthreads();
    }
    if (t == 0) out[0] = s[0] / ((float)N_ROWS * TEMPC);
}

extern "C" void kernel_launch(void* const* d_in, const int* in_sizes, int n_in,
                              void* d_out, int out_size)
{
    const float4* a4 = (const float4*)d_in[0];  // online_output [16384, 1024] f32
    const float4* b4 = (const float4*)d_in[1];  // target_output [16384, 1024] f32
    float* out = (float*)d_out;

    byol_row_kernel<<<N_ROWS, 256>>>(a4, b4);
    byol_reduce_kernel<<<1, 1024>>>(out);
}

// round 2
// speedup vs baseline: 1.0749x; 1.0749x over previous
#include <cuda_runtime.h>

#define N_ROWS   16384
#define D        1024
#define D4       (D / 4)          // 256 float4 per row
#define TEMPC    0.05f
#define EPSC     1e-8f

#define THREADS      256
#define WARPS_CTA    8
#define ROWS_PER_WARP 2
#define ROWS_PER_CTA (WARPS_CTA * ROWS_PER_WARP)      // 16
#define GRID         (N_ROWS / ROWS_PER_CTA)          // 1024
#define F4_PER_LANE  (D4 / 32)                        // 8

__device__ float g_partial[GRID];
__device__ unsigned int g_count = 0;

__global__ __launch_bounds__(THREADS) void byol_fused_kernel(
    const float4* __restrict__ a4, const float4* __restrict__ b4,
    float* __restrict__ out)
{
    const int t   = threadIdx.x;
    const int wid = t >> 5;
    const int lid = t & 31;

    float loss = 0.f;   // meaningful on lane 0 of each warp

    #pragma unroll
    for (int r = 0; r < ROWS_PER_WARP; r++) {
        const int row = blockIdx.x * ROWS_PER_CTA + wid * ROWS_PER_WARP + r;
        const long base = (long)row * D4 + lid;

        // 8 independent float4 loads per input per row -> high MLP
        float4 av[F4_PER_LANE], bv[F4_PER_LANE];
        #pragma unroll
        for (int j = 0; j < F4_PER_LANE; j++) av[j] = a4[base + 32 * j];
        #pragma unroll
        for (int j = 0; j < F4_PER_LANE; j++) bv[j] = b4[base + 32 * j];

        float dot = 0.f, aa = 0.f, bb = 0.f;
        #pragma unroll
        for (int j = 0; j < F4_PER_LANE; j++) {
            dot += av[j].x * bv[j].x + av[j].y * bv[j].y
                 + av[j].z * bv[j].z + av[j].w * bv[j].w;
            aa  += av[j].x * av[j].x + av[j].y * av[j].y
                 + av[j].z * av[j].z + av[j].w * av[j].w;
            bb  += bv[j].x * bv[j].x + bv[j].y * bv[j].y
                 + bv[j].z * bv[j].z + bv[j].w * bv[j].w;
        }

        #pragma unroll
        for (int off = 16; off > 0; off >>= 1) {
            dot += __shfl_xor_sync(0xffffffffu, dot, off);
            aa  += __shfl_xor_sync(0xffffffffu, aa,  off);
            bb  += __shfl_xor_sync(0xffffffffu, bb,  off);
        }

        if (lid == 0) {
            const float n1 = fmaxf(sqrtf(aa), EPSC);
            const float n2 = fmaxf(sqrtf(bb), EPSC);
            loss += 2.0f - 2.0f * (dot / (n1 * n2));
        }
    }

    // CTA-level combine of the 8 warp sums (fixed order -> deterministic)
    __shared__ float s_warp[WARPS_CTA];
    __shared__ bool  s_last;
    if (lid == 0) s_warp[wid] = loss;
    __syncthreads();

    if (t == 0) {
        float p = 0.f;
        #pragma unroll
        for (int w = 0; w < WARPS_CTA; w++) p += s_warp[w];
        g_partial[blockIdx.x] = p;
        __threadfence();
        const unsigned int prev = atomicAdd(&g_count, 1u);
        s_last = (prev == GRID - 1);
    }
    __syncthreads();

    // Last CTA: deterministic tree reduce of the 1024 partials
    if (s_last) {
        __shared__ float s[THREADS];
        float sum = 0.f;
        #pragma unroll
        for (int i = 0; i < GRID / THREADS; i++)       // 4 each, fixed order
            sum += g_partial[t + i * THREADS];
        s[t] = sum;
        __syncthreads();
        #pragma unroll
        for (int off = THREADS / 2; off > 0; off >>= 1) {
            if (t < off) s[t] += s[t + off];
            __syncthreads();
        }
        if (t == 0) {
            out[0] = s[0] / ((float)N_ROWS * TEMPC);
            g_count = 0;   // reset for next (graph-replayed) call
        }
    }
}

extern "C" void kernel_launch(void* const* d_in, const int* in_sizes, int n_in,
                              void* d_out, int out_size)
{
    const float4* a4 = (const float4*)d_in[0];  // online_output [16384,1024] f32
    const float4* b4 = (const float4*)d_in[1];  // target_output [16384,1024] f32
    float* out = (float*)d_out;

    byol_fused_kernel<<<GRID, THREADS>>>(a4, b4, out);
}